// round 4
// baseline (speedup 1.0000x reference)
#include <cuda_runtime.h>
#include <math.h>

#define NUM_CLASSES 10
#define BLOCK 256
#define GRID 592                       // 148(+) SMs * 4 — guaranteed co-resident via launch_bounds
#define NTHREADS (GRID * BLOCK)

// log(x) = logf(x * 2^-21) + 21*ln2  (shift folded into final math)
#define LOG_SCALE (4.76837158203125e-7f)   // 2^-21
#define LOG_SHIFT 21.0

__device__ float  g_hist_partial[GRID * NUM_CLASSES];
__device__ double g_partial_log[GRID];
__device__ double g_partial_sq[GRID];
__device__ unsigned int g_hist_ready = 0;  // reset by last block each run
__device__ unsigned int g_done = 0;        // reset by last block each run

__global__ void __launch_bounds__(BLOCK, 4)
cse_fused_kernel(const float* __restrict__ outp, const int* __restrict__ tgt,
                 int n_rows, float* __restrict__ out) {
    __shared__ unsigned int s_hist[NUM_CLASSES];
    __shared__ float  s_cnt[NUM_CLASSES];
    __shared__ double s_rl[BLOCK / 32];
    __shared__ double s_rq[BLOCK / 32];
    __shared__ bool s_last;

    const int tid = threadIdx.x;
    const int bid = blockIdx.x;

    // ================= Phase A: histogram of target (int32 in [0,10)) ======
    if (tid < NUM_CLASSES) s_hist[tid] = 0u;
    if (tid < NUM_CLASSES) s_cnt[tid] = 0.0f;
    __syncthreads();
    {
        unsigned int c[NUM_CLASSES];
#pragma unroll
        for (int j = 0; j < NUM_CLASSES; j++) c[j] = 0u;

        const int4* t4 = reinterpret_cast<const int4*>(tgt);
        const int n4 = n_rows >> 2;
        unsigned long long acc = 0ull;
        int since = 0;
        for (int i = bid * BLOCK + tid; i < n4; i += NTHREADS) {
            int4 v = __ldcs(&t4[i]);
            acc += 1ull << (6 * v.x);
            acc += 1ull << (6 * v.y);
            acc += 1ull << (6 * v.z);
            acc += 1ull << (6 * v.w);
            if (++since == 10) {          // <=40 increments per 6-bit field
#pragma unroll
                for (int j = 0; j < NUM_CLASSES; j++)
                    c[j] += (unsigned int)((acc >> (6 * j)) & 63ull);
                acc = 0ull; since = 0;
            }
        }
        if (since) {
#pragma unroll
            for (int j = 0; j < NUM_CLASSES; j++)
                c[j] += (unsigned int)((acc >> (6 * j)) & 63ull);
        }
        if (bid == 0 && tid == 0) {       // tail rows (n % 4)
            for (int r = (n_rows >> 2) << 2; r < n_rows; r++) c[tgt[r]]++;
        }
#pragma unroll
        for (int j = 0; j < NUM_CLASSES; j++)
            if (c[j]) atomicAdd(&s_hist[j], c[j]);
    }
    __syncthreads();
    if (tid < NUM_CLASSES)
        g_hist_partial[bid * NUM_CLASSES + tid] = (float)s_hist[tid];
    __threadfence();
    if (tid == 0) {
        atomicAdd(&g_hist_ready, 1u);
        // spin until all blocks published (all GRID blocks are co-resident)
        while (*(volatile unsigned int*)&g_hist_ready < (unsigned int)GRID)
            __nanosleep(64);
        __threadfence();
    }
    __syncthreads();

    // reduce partials -> class counts (exact small integers in float)
    for (int idx = tid; idx < GRID * NUM_CLASSES; idx += BLOCK)
        atomicAdd(&s_cnt[idx % NUM_CLASSES], g_hist_partial[idx]);
    __syncthreads();

    float c[NUM_CLASSES];
#pragma unroll
    for (int j = 0; j < NUM_CLASSES; j++) c[j] = s_cnt[j];

    // ================= Phase B: one streaming pass over outputs =============
    // Thread handles 2 consecutive rows = 80B = 5 aligned float4 loads, no smem,
    // no barriers -> warps free-run, loads stay in flight.
    const float4* __restrict__ in4 = reinterpret_cast<const float4*>(outp);
    const int n_pairs = n_rows >> 1;

    double acc_log = 0.0;
    double acc_sq  = 0.0;
    float  prod    = 1.0f;
    int    pcnt    = 0;

    for (int p = bid * BLOCK + tid; p < n_pairs; p += NTHREADS) {
        const size_t q = (size_t)p * 5;
        float4 a0 = in4[q + 0];
        float4 a1 = in4[q + 1];
        float4 a2 = in4[q + 2];
        float4 a3 = in4[q + 3];
        float4 a4 = in4[q + 4];

        float v[20] = {a0.x, a0.y, a0.z, a0.w, a1.x, a1.y, a1.z, a1.w,
                       a2.x, a2.y, a2.z, a2.w, a3.x, a3.y, a3.z, a3.w,
                       a4.x, a4.y, a4.z, a4.w};

        float dot0 = 0.f, dot1 = 0.f, sq = 0.f;
#pragma unroll
        for (int j = 0; j < NUM_CLASSES; j++) {
            dot0 = fmaf(v[j], c[j], dot0);
            dot1 = fmaf(v[NUM_CLASSES + j], c[j], dot1);
        }
#pragma unroll
        for (int k = 0; k < 20; k++) sq = fmaf(v[k], v[k], sq);
        acc_sq += (double)sq;

        prod *= dot0 * LOG_SCALE;
        if (++pcnt == 8) { acc_log += (double)logf(prod); prod = 1.0f; pcnt = 0; }
        prod *= dot1 * LOG_SCALE;
        if (++pcnt == 8) { acc_log += (double)logf(prod); prod = 1.0f; pcnt = 0; }
    }

    // odd trailing row (n_rows odd — not expected for N=2^22)
    if ((n_rows & 1) && bid == 0 && tid == 0) {
        const float* row = outp + (size_t)(n_rows - 1) * NUM_CLASSES;
        float dot = 0.f, sq = 0.f;
#pragma unroll
        for (int j = 0; j < NUM_CLASSES; j++) {
            float x = row[j];
            dot = fmaf(x, c[j], dot);
            sq  = fmaf(x, x, sq);
        }
        acc_sq  += (double)sq;
        acc_log += (double)logf(dot * LOG_SCALE);
    }

    if (pcnt) acc_log += (double)logf(prod);

    // ================= block reduction (deterministic order) ===============
#pragma unroll
    for (int off = 16; off; off >>= 1) {
        acc_log += __shfl_down_sync(0xffffffffu, acc_log, off);
        acc_sq  += __shfl_down_sync(0xffffffffu, acc_sq,  off);
    }
    const int wid = tid >> 5, lane = tid & 31;
    if (lane == 0) { s_rl[wid] = acc_log; s_rq[wid] = acc_sq; }
    __syncthreads();
    if (tid == 0) {
        double a = 0.0, b = 0.0;
#pragma unroll
        for (int w = 0; w < BLOCK / 32; w++) { a += s_rl[w]; b += s_rq[w]; }
        g_partial_log[bid] = a;
        g_partial_sq[bid]  = b;
        __threadfence();
        unsigned int t = atomicAdd(&g_done, 1u);
        s_last = (t == (unsigned int)(GRID - 1));
    }
    __syncthreads();

    // ================= last block: final scalar =============================
    if (s_last) {
        __threadfence();
        double a = 0.0, b = 0.0;
        for (int i = tid; i < GRID; i += BLOCK) {
            a += g_partial_log[i];
            b += g_partial_sq[i];
        }
#pragma unroll
        for (int off = 16; off; off >>= 1) {
            a += __shfl_down_sync(0xffffffffu, a, off);
            b += __shfl_down_sync(0xffffffffu, b, off);
        }
        if (lane == 0) { s_rl[wid] = a; s_rq[wid] = b; }
        __syncthreads();
        if (tid == 0) {
            double sa = 0.0, sb = 0.0;
#pragma unroll
            for (int w = 0; w < BLOCK / 32; w++) { sa += s_rl[w]; sb += s_rq[w]; }
            double N = (double)n_rows;
            double mean_log_nom = sa / N + LOG_SHIFT * M_LN2;
            double log_denom = 0.5 * log(sb) + 0.5 * log(N);   // log(||o||_F * sqrt(N))
            out[0] = (float)(log_denom - mean_log_nom);
            g_done = 0;         // reset for next graph replay
            g_hist_ready = 0;
        }
    }
}

extern "C" void kernel_launch(void* const* d_in, const int* in_sizes, int n_in,
                              void* d_out, int out_size) {
    // Resolve inputs by size: outputs has NUM_CLASSES x the elements of target.
    int io = 0, it = 1;
    if (n_in >= 2 && in_sizes[1] > in_sizes[0]) { io = 1; it = 0; }
    const float* outputs = (const float*)d_in[io];
    const int*   tgt     = (const int*)d_in[it];      // int32
    const int    n_rows  = in_sizes[it];              // N samples
    float* out           = (float*)d_out;

    cse_fused_kernel<<<GRID, BLOCK>>>(outputs, tgt, n_rows, out);
}